// round 7
// baseline (speedup 1.0000x reference)
#include <cuda_runtime.h>
#include <cuda_bf16.h>

// ODEfunc: dy = tanh(y@W1 + t*wt + b1) @ W2 + b2 ; div_i = sum_h sech2(z_h)*c_h
// with c_h = sum_d W1[d,h]*W2[h,d]  (analytic trace of the Jacobian).
// Output: [N, D+1] = [dy | -div]
//
// R6 -> R7: inner loop processes 2 h-values per body as a dependency ladder so
// the MUFU (ex2/rcp) chains of one h overlap the FMA/LDS work of the other.
// Activation: e = ex2(K*z), K=2/ln2; u = 2*rcp(e+1); a = 1-u; sech2 = u*(2-u).

#define N_SAMP 8192
#define D_DIM  64
#define H_DIM  256

#define SAMP_PER_BLK 64
#define WSTRIDE 68     // floats; 272B rows -> 16B aligned, conflict-free row reads
#define TSTRIDE 260    // scratch transpose tile row stride (floats), 16B aligned

typedef unsigned long long ull;

__device__ __forceinline__ ull pack2(float lo, float hi) {
    ull r; asm("mov.b64 %0, {%1, %2};" : "=l"(r) : "f"(lo), "f"(hi)); return r;
}
__device__ __forceinline__ void unpack2(ull v, float& lo, float& hi) {
    asm("mov.b64 {%0, %1}, %2;" : "=f"(lo), "=f"(hi) : "l"(v));
}
__device__ __forceinline__ float rcp_approx(float x) {
    float r; asm("rcp.approx.f32 %0, %1;" : "=f"(r) : "f"(x)); return r;
}
__device__ __forceinline__ float ex2_approx(float x) {
    float r; asm("ex2.approx.f32 %0, %1;" : "=f"(r) : "f"(x)); return r;
}
#define FMA2(d, a, b, c) asm("fma.rn.f32x2 %0, %1, %2, %3;" : "=l"(d) : "l"(a), "l"(b), "l"(c))

__global__ void __launch_bounds__(256, 1)
ode_fused_kernel(const float* __restrict__ t_in,
                 const float* __restrict__ y_g,
                 const float* __restrict__ W1_g,   // [D, H] row-major
                 const float* __restrict__ b1_g,   // [H]
                 const float* __restrict__ wt_g,   // [H]
                 const float* __restrict__ W2_g,   // [H, D] row-major
                 const float* __restrict__ b2_g,   // [D]
                 float* __restrict__ out)          // [N, D+1]
{
    extern __shared__ float sm[];
    float*  W1T   = sm;                          // [H][WSTRIDE]; later reused as P partial tile
    float*  W2s   = W1T + H_DIM * WSTRIDE;       // [H][WSTRIDE]; first used as transpose scratch T
    float2* metas = (float2*)(W2s + H_DIM * WSTRIDE); // [H] : {t*wt+b1, c_h}
    float*  b2s   = (float*)(metas + H_DIM);     // [D]
    float*  T     = W2s;                         // scratch: [D][TSTRIDE]

    const int tid  = threadIdx.x;
    const int lane = tid & 31;
    const int wid  = tid >> 5;
    const int q    = wid & 3;    // h-chunk 0..3
    const int set  = wid >> 2;   // sample set 0/1
    const int sloc = set * 32 + lane;                    // local sample 0..63
    const int sg   = blockIdx.x * SAMP_PER_BLK + sloc;   // global sample

    const float t = t_in[0];
    const float K = 2.8853900817779268f;  // 2/ln(2): tanh(z) via ex2(K*z)

    // ---- load y (packed pairs) early; overlaps with smem staging ----
    ull yp[32];
    {
        const ulonglong2* yv = (const ulonglong2*)(y_g + sg * D_DIM);
        #pragma unroll
        for (int i = 0; i < 16; i++) {
            ulonglong2 v = yv[i];
            yp[2*i+0] = v.x; yp[2*i+1] = v.y;
        }
    }

    // ---- Step A: W1 [k][h] -> scratch T[k][h] (coalesced LDG.128, conflict-free STS.128) ----
    {
        const float4* w1v = (const float4*)W1_g;
        #pragma unroll
        for (int j = 0; j < 16; j++) {
            int v  = tid + 256 * j;     // float4 index, 0..4095
            int k  = v >> 6;            // 0..63
            int hq = v & 63;            // float4 within row
            *(float4*)(T + k * TSTRIDE + 4 * hq) = w1v[v];
        }
    }
    __syncthreads();

    // ---- Step B: transpose T -> W1T[h][k] (stride-1 LDS reads, conflict-free STS.128) ----
    {
        const int h = tid;              // each thread owns one output row
        #pragma unroll
        for (int j = 0; j < 16; j++) {  // k-quad
            float4 r;
            r.x = T[(4*j + 0) * TSTRIDE + h];
            r.y = T[(4*j + 1) * TSTRIDE + h];
            r.z = T[(4*j + 2) * TSTRIDE + h];
            r.w = T[(4*j + 3) * TSTRIDE + h];
            *(float4*)(W1T + h * WSTRIDE + 4*j) = r;
        }
    }
    __syncthreads();   // T reads done -> safe to overwrite with W2s

    // ---- W2 [h][d] -> W2s[h][d] (coalesced LDG.128, conflict-free STS.128) ----
    {
        const float4* w2v = (const float4*)W2_g;
        #pragma unroll
        for (int j = 0; j < 16; j++) {
            int v  = tid + 256 * j;     // float4 index, 0..4095
            int h  = v >> 4;
            int dq = v & 15;
            *(float4*)(W2s + h * WSTRIDE + 4 * dq) = w2v[v];
        }
        if (tid < D_DIM) b2s[tid] = b2_g[tid];
    }
    __syncthreads();

    // ---- per-h meta: bias (t*wt+b1) and Jacobian-trace weight c_h ----
    {
        int h = tid; // 256 threads == H
        const float4* u4 = (const float4*)(W1T + h * WSTRIDE);
        const float4* v4 = (const float4*)(W2s + h * WSTRIDE);
        float ca = 0.f, cb = 0.f, cc = 0.f, cd = 0.f;
        #pragma unroll
        for (int k = 0; k < 16; k++) {
            float4 u = u4[k], v = v4[k];
            ca += u.x * v.x; cb += u.y * v.y; cc += u.z * v.z; cd += u.w * v.w;
        }
        metas[h] = make_float2(fmaf(t, wt_g[h], b1_g[h]), (ca + cb) + (cc + cd));
    }
    __syncthreads();

    // ---- main fused loop: 2 h-values per body, ladder-scheduled ----
    ull dyp[32];
    #pragma unroll
    for (int d = 0; d < 32; d++) dyp[d] = 0ull;
    float divacc = 0.f;

    const int h0 = q * 64;
    #pragma unroll 1
    for (int hh = 0; hh < 32; hh++) {
        const int ha = h0 + 2 * hh;
        const int hb = ha + 1;
        const ulonglong2* w1a = (const ulonglong2*)(W1T + ha * WSTRIDE);
        const ulonglong2* w1b = (const ulonglong2*)(W1T + hb * WSTRIDE);

        // --- z for ha ---
        ull za0 = 0ull, za1 = 0ull, za2 = 0ull, za3 = 0ull;
        #pragma unroll
        for (int k = 0; k < 8; k++) {
            ulonglong2 wa = w1a[2*k];
            ulonglong2 wb = w1a[2*k+1];
            FMA2(za0, yp[4*k+0], wa.x, za0);
            FMA2(za1, yp[4*k+1], wa.y, za1);
            FMA2(za2, yp[4*k+2], wb.x, za2);
            FMA2(za3, yp[4*k+3], wb.y, za3);
        }
        float2 ma = metas[ha];
        float p0,p1,p2,p3,p4,p5,p6,p7;
        unpack2(za0,p0,p1); unpack2(za1,p2,p3); unpack2(za2,p4,p5); unpack2(za3,p6,p7);
        float sa = (((p0+p1)+(p2+p3)) + ((p4+p5)+(p6+p7))) + ma.x;
        float ea = ex2_approx(K * sa);                  // MUFU chain A starts

        // --- z for hb: its FMAs execute under ea's latency ---
        ull zb0 = 0ull, zb1 = 0ull, zb2 = 0ull, zb3 = 0ull;
        #pragma unroll
        for (int k = 0; k < 8; k++) {
            ulonglong2 wa = w1b[2*k];
            ulonglong2 wb = w1b[2*k+1];
            FMA2(zb0, yp[4*k+0], wa.x, zb0);
            FMA2(zb1, yp[4*k+1], wa.y, zb1);
            FMA2(zb2, yp[4*k+2], wb.x, zb2);
            FMA2(zb3, yp[4*k+3], wb.y, zb3);
        }
        float2 mb = metas[hb];
        unpack2(zb0,p0,p1); unpack2(zb1,p2,p3); unpack2(zb2,p4,p5); unpack2(zb3,p6,p7);
        float sb = (((p0+p1)+(p2+p3)) + ((p4+p5)+(p6+p7))) + mb.x;

        float ua = 2.0f * rcp_approx(ea + 1.0f);        // MUFU chain A continues
        float eb = ex2_approx(K * sb);                  // MUFU chain B starts
        float aa = 1.0f - ua;
        divacc = fmaf(ua * (2.0f - ua), ma.y, divacc);

        // --- dy += aa * W2[ha] : executes under eb's latency ---
        ull aap = pack2(aa, aa);
        const ulonglong2* w2a = (const ulonglong2*)(W2s + ha * WSTRIDE);
        #pragma unroll
        for (int k = 0; k < 16; k++) {
            ulonglong2 w = w2a[k];
            FMA2(dyp[2*k+0], aap, w.x, dyp[2*k+0]);
            FMA2(dyp[2*k+1], aap, w.y, dyp[2*k+1]);
        }

        float ub = 2.0f * rcp_approx(eb + 1.0f);        // MUFU chain B continues
        float ab = 1.0f - ub;
        divacc = fmaf(ub * (2.0f - ub), mb.y, divacc);

        // --- dy += ab * W2[hb] : overlaps next iteration's loads ---
        ull abp = pack2(ab, ab);
        const ulonglong2* w2b = (const ulonglong2*)(W2s + hb * WSTRIDE);
        #pragma unroll
        for (int k = 0; k < 16; k++) {
            ulonglong2 w = w2b[k];
            FMA2(dyp[2*k+0], abp, w.x, dyp[2*k+0]);
            FMA2(dyp[2*k+1], abp, w.y, dyp[2*k+1]);
        }
    }

    // ---- parallel epilogue: 4 partials written concurrently into P (reuses W1T), one gather ----
    float* P = W1T;   // rows: row = q*64 + sloc, cols 0..63 = dy, col 64 = -div
    __syncthreads();  // all W1T reads complete before overwrite
    {
        // 272B row base -> 16B aligned: write partials as STS.128
        ulonglong2* Prow = (ulonglong2*)(P + (q * 64 + sloc) * WSTRIDE);
        #pragma unroll
        for (int d = 0; d < 16; d++) {
            ulonglong2 v; v.x = dyp[2*d]; v.y = dyp[2*d+1];
            Prow[d] = v;
        }
        ((float*)Prow)[64] = -divacc;
    }
    __syncthreads();

    // gather: out[s][d] = sum_q P[q][s][d] (+ b2[d] for d<64), coalesced store
    {
        float* outp = out + (size_t)blockIdx.x * SAMP_PER_BLK * (D_DIM + 1);
        for (int i = tid; i < SAMP_PER_BLK * (D_DIM + 1); i += 256) {
            int s = i / (D_DIM + 1);
            int d = i - s * (D_DIM + 1);
            const float* col = P + s * WSTRIDE + d;
            float v = (col[0] + col[64 * WSTRIDE])
                    + (col[128 * WSTRIDE] + col[192 * WSTRIDE]);
            if (d < D_DIM) v += b2s[d];
            outp[i] = v;
        }
    }
}

extern "C" void kernel_launch(void* const* d_in, const int* in_sizes, int n_in,
                              void* d_out, int out_size)
{
    const float* t  = (const float*)d_in[0];
    const float* y  = (const float*)d_in[1];
    const float* W1 = (const float*)d_in[2];
    const float* b1 = (const float*)d_in[3];
    const float* wt = (const float*)d_in[4];
    const float* W2 = (const float*)d_in[5];
    const float* b2 = (const float*)d_in[6];
    float* out = (float*)d_out;

    const int smem_bytes =
        (H_DIM * WSTRIDE * 2) * 4      // W1T + W2s (W2s region doubles as transpose scratch)
        + H_DIM * 8                    // metas (float2)
        + D_DIM * 4;                   // b2

    cudaFuncSetAttribute(ode_fused_kernel,
                         cudaFuncAttributeMaxDynamicSharedMemorySize, smem_bytes);

    dim3 grid(N_SAMP / SAMP_PER_BLK);   // 128
    dim3 block(256);
    ode_fused_kernel<<<grid, block, smem_bytes>>>(t, y, W1, b1, wt, W2, b2, out);
}

// round 13
// speedup vs baseline: 1.0761x; 1.0761x over previous
#include <cuda_runtime.h>
#include <cuda_bf16.h>

// ODEfunc: dy = tanh(y@W1 + t*wt + b1) @ W2 + b2 ; div_i = sum_h sech2(z_h)*c_h
// with c_h = sum_d W1[d,h]*W2[h,d]  (analytic trace of the Jacobian).
// Output: [N, D+1] = [dy | -div]
//
// 2 samples per thread, half-D per thread (lane pairs l, l^16 own the two
// D-halves). Each weight LDS.128 feeds 4 packed FMAs instead of 2, halving
// smem crossbar traffic (the R7-measured bottleneck: L1=64% vs fma=28%).
// z-halves combined with one shfl_xor per (sample,h).

#define N_SAMP 8192
#define D_DIM  64
#define H_DIM  256

#define SAMP_PER_BLK 64
#define WSTRIDE 68     // floats; 272B rows -> 16B aligned
#define TSTRIDE 260    // scratch transpose tile row stride (floats)

typedef unsigned long long ull;

__device__ __forceinline__ ull pack2(float lo, float hi) {
    ull r; asm("mov.b64 %0, {%1, %2};" : "=l"(r) : "f"(lo), "f"(hi)); return r;
}
__device__ __forceinline__ void unpack2(ull v, float& lo, float& hi) {
    asm("mov.b64 {%0, %1}, %2;" : "=f"(lo), "=f"(hi) : "l"(v));
}
__device__ __forceinline__ float rcp_approx(float x) {
    float r; asm("rcp.approx.f32 %0, %1;" : "=f"(r) : "f"(x)); return r;
}
__device__ __forceinline__ float ex2_approx(float x) {
    float r; asm("ex2.approx.f32 %0, %1;" : "=f"(r) : "f"(x)); return r;
}
#define FMA2(d, a, b, c) asm("fma.rn.f32x2 %0, %1, %2, %3;" : "=l"(d) : "l"(a), "l"(b), "l"(c))

__global__ void __launch_bounds__(256, 1)
ode_fused_kernel(const float* __restrict__ t_in,
                 const float* __restrict__ y_g,
                 const float* __restrict__ W1_g,   // [D, H] row-major
                 const float* __restrict__ b1_g,   // [H]
                 const float* __restrict__ wt_g,   // [H]
                 const float* __restrict__ W2_g,   // [H, D] row-major
                 const float* __restrict__ b2_g,   // [D]
                 float* __restrict__ out)          // [N, D+1]
{
    extern __shared__ float sm[];
    float*  W1T   = sm;                          // [H][WSTRIDE]; later reused as P partial tile
    float*  W2s   = W1T + H_DIM * WSTRIDE;       // [H][WSTRIDE]; first used as transpose scratch T
    float2* metas = (float2*)(W2s + H_DIM * WSTRIDE); // [H] : {t*wt+b1, c_h}
    float*  b2s   = (float*)(metas + H_DIM);     // [D]
    float*  T     = W2s;                         // scratch: [D][TSTRIDE]

    const int tid  = threadIdx.x;
    const int lane = tid & 31;
    const int wid  = tid >> 5;
    const int q    = wid >> 1;     // h-chunk 0..3 (64 h each)
    const int set  = wid & 1;      // sample 32-group 0/1
    const int p    = lane & 15;    // sample-pair index
    const int half = lane >> 4;    // D-half 0/1
    const int slA  = set * 32 + p;         // local sample A (0..63)
    const int slB  = slA + 16;             // local sample B
    const int sgA  = blockIdx.x * SAMP_PER_BLK + slA;

    const float t = t_in[0];
    const float K = 2.8853900817779268f;   // 2/ln(2)

    // ---- load y halves for both samples (16 ull each) ----
    ull ya[16], yb[16];
    {
        const ulonglong2* A = (const ulonglong2*)(y_g + (size_t)sgA * D_DIM + half * 32);
        const ulonglong2* B = (const ulonglong2*)(y_g + (size_t)(sgA + 16) * D_DIM + half * 32);
        #pragma unroll
        for (int i = 0; i < 8; i++) {
            ulonglong2 a = A[i], b = B[i];
            ya[2*i] = a.x; ya[2*i+1] = a.y;
            yb[2*i] = b.x; yb[2*i+1] = b.y;
        }
    }

    // ---- Step A: W1 [k][h] -> scratch T[k][h] (coalesced LDG.128, conflict-free STS.128) ----
    {
        const float4* w1v = (const float4*)W1_g;
        #pragma unroll
        for (int j = 0; j < 16; j++) {
            int v  = tid + 256 * j;
            int k  = v >> 6;
            int hq = v & 63;
            *(float4*)(T + k * TSTRIDE + 4 * hq) = w1v[v];
        }
    }
    __syncthreads();

    // ---- Step B: transpose T -> W1T[h][k] ----
    {
        const int h = tid;
        #pragma unroll
        for (int j = 0; j < 16; j++) {
            float4 r;
            r.x = T[(4*j + 0) * TSTRIDE + h];
            r.y = T[(4*j + 1) * TSTRIDE + h];
            r.z = T[(4*j + 2) * TSTRIDE + h];
            r.w = T[(4*j + 3) * TSTRIDE + h];
            *(float4*)(W1T + h * WSTRIDE + 4*j) = r;
        }
    }
    __syncthreads();   // T reads done -> safe to overwrite with W2s

    // ---- W2 [h][d] -> W2s[h][d] ----
    {
        const float4* w2v = (const float4*)W2_g;
        #pragma unroll
        for (int j = 0; j < 16; j++) {
            int v  = tid + 256 * j;
            int h  = v >> 4;
            int dq = v & 15;
            *(float4*)(W2s + h * WSTRIDE + 4 * dq) = w2v[v];
        }
        if (tid < D_DIM) b2s[tid] = b2_g[tid];
    }
    __syncthreads();

    // ---- per-h meta: bias (t*wt+b1) and Jacobian-trace weight c_h ----
    {
        int h = tid;
        const float4* u4 = (const float4*)(W1T + h * WSTRIDE);
        const float4* v4 = (const float4*)(W2s + h * WSTRIDE);
        float ca = 0.f, cb = 0.f, cc = 0.f, cd = 0.f;
        #pragma unroll
        for (int k = 0; k < 16; k++) {
            float4 u = u4[k], v = v4[k];
            ca += u.x * v.x; cb += u.y * v.y; cc += u.z * v.z; cd += u.w * v.w;
        }
        metas[h] = make_float2(fmaf(t, wt_g[h], b1_g[h]), (ca + cb) + (cc + cd));
    }
    __syncthreads();

    // ---- main loop: 2 h per body, 2 samples per thread, half-D each ----
    ull dyA[16], dyB[16];
    #pragma unroll
    for (int d = 0; d < 16; d++) { dyA[d] = 0ull; dyB[d] = 0ull; }
    float divA = 0.f, divB = 0.f;

    const int h0 = q * 64;
    #pragma unroll 1
    for (int i = 0; i < 32; i++) {
        const int ha = h0 + 2 * i;
        const int hb = ha + 1;

        // --- z halves for ha (both samples): 32 FMA2, 8 LDS.128 ---
        const ulonglong2* w1a = (const ulonglong2*)(W1T + ha * WSTRIDE + half * 32);
        ull uA0 = 0ull, uA1 = 0ull, vA0 = 0ull, vA1 = 0ull;
        #pragma unroll
        for (int k = 0; k < 8; k++) {
            ulonglong2 w = w1a[k];
            FMA2(uA0, ya[2*k+0], w.x, uA0);
            FMA2(uA1, ya[2*k+1], w.y, uA1);
            FMA2(vA0, yb[2*k+0], w.x, vA0);
            FMA2(vA1, yb[2*k+1], w.y, vA1);
        }
        float2 ma = metas[ha];
        float x0, x1, x2, x3;
        unpack2(uA0, x0, x1); unpack2(uA1, x2, x3);
        float zAh = (x0 + x1) + (x2 + x3);
        unpack2(vA0, x0, x1); unpack2(vA1, x2, x3);
        float zBh = (x0 + x1) + (x2 + x3);
        zAh += __shfl_xor_sync(0xffffffffu, zAh, 16);
        zBh += __shfl_xor_sync(0xffffffffu, zBh, 16);
        float eA = ex2_approx(K * (zAh + ma.x));       // MUFU chains ha start
        float eB = ex2_approx(K * (zBh + ma.x));

        // --- z halves for hb: execute under ha's MUFU latency ---
        const ulonglong2* w1b = (const ulonglong2*)(W1T + hb * WSTRIDE + half * 32);
        ull uB0 = 0ull, uB1 = 0ull, vB0 = 0ull, vB1 = 0ull;
        #pragma unroll
        for (int k = 0; k < 8; k++) {
            ulonglong2 w = w1b[k];
            FMA2(uB0, ya[2*k+0], w.x, uB0);
            FMA2(uB1, ya[2*k+1], w.y, uB1);
            FMA2(vB0, yb[2*k+0], w.x, vB0);
            FMA2(vB1, yb[2*k+1], w.y, vB1);
        }
        float2 mb = metas[hb];
        unpack2(uB0, x0, x1); unpack2(uB1, x2, x3);
        float zAh2 = (x0 + x1) + (x2 + x3);
        unpack2(vB0, x0, x1); unpack2(vB1, x2, x3);
        float zBh2 = (x0 + x1) + (x2 + x3);
        zAh2 += __shfl_xor_sync(0xffffffffu, zAh2, 16);
        zBh2 += __shfl_xor_sync(0xffffffffu, zBh2, 16);

        float uAa = 2.0f * rcp_approx(eA + 1.0f);      // ha MUFU chains continue
        float uBa = 2.0f * rcp_approx(eB + 1.0f);
        float eA2 = ex2_approx(K * (zAh2 + mb.x));     // hb MUFU chains start
        float eB2 = ex2_approx(K * (zBh2 + mb.x));
        float aA = 1.0f - uAa;
        float aB = 1.0f - uBa;
        divA = fmaf(uAa * (2.0f - uAa), ma.y, divA);
        divB = fmaf(uBa * (2.0f - uBa), ma.y, divB);

        // --- dy += a * W2[ha] (halves): 32 FMA2, 8 LDS.128; covers hb MUFU ---
        ull aAp = pack2(aA, aA), aBp = pack2(aB, aB);
        const ulonglong2* w2a = (const ulonglong2*)(W2s + ha * WSTRIDE + half * 32);
        #pragma unroll
        for (int k = 0; k < 8; k++) {
            ulonglong2 w = w2a[k];
            FMA2(dyA[2*k+0], aAp, w.x, dyA[2*k+0]);
            FMA2(dyA[2*k+1], aAp, w.y, dyA[2*k+1]);
            FMA2(dyB[2*k+0], aBp, w.x, dyB[2*k+0]);
            FMA2(dyB[2*k+1], aBp, w.y, dyB[2*k+1]);
        }

        float uA2 = 2.0f * rcp_approx(eA2 + 1.0f);
        float uB2 = 2.0f * rcp_approx(eB2 + 1.0f);
        float aA2 = 1.0f - uA2;
        float aB2 = 1.0f - uB2;
        divA = fmaf(uA2 * (2.0f - uA2), mb.y, divA);
        divB = fmaf(uB2 * (2.0f - uB2), mb.y, divB);

        // --- dy += a * W2[hb] (halves): overlaps next iteration's loads ---
        ull aA2p = pack2(aA2, aA2), aB2p = pack2(aB2, aB2);
        const ulonglong2* w2b = (const ulonglong2*)(W2s + hb * WSTRIDE + half * 32);
        #pragma unroll
        for (int k = 0; k < 8; k++) {
            ulonglong2 w = w2b[k];
            FMA2(dyA[2*k+0], aA2p, w.x, dyA[2*k+0]);
            FMA2(dyA[2*k+1], aA2p, w.y, dyA[2*k+1]);
            FMA2(dyB[2*k+0], aB2p, w.x, dyB[2*k+0]);
            FMA2(dyB[2*k+1], aB2p, w.y, dyB[2*k+1]);
        }
    }

    // ---- parallel epilogue: partials into P (reuses W1T), one gather ----
    float* P = W1T;   // row = q*64 + local_sample, cols [half*32, half*32+32), col 64 = -div
    __syncthreads();  // all W1T reads complete before overwrite
    {
        ulonglong2* rowA = (ulonglong2*)(P + (q * 64 + slA) * WSTRIDE + half * 32);
        ulonglong2* rowB = (ulonglong2*)(P + (q * 64 + slB) * WSTRIDE + half * 32);
        #pragma unroll
        for (int k = 0; k < 8; k++) {
            ulonglong2 a; a.x = dyA[2*k]; a.y = dyA[2*k+1];
            ulonglong2 b; b.x = dyB[2*k]; b.y = dyB[2*k+1];
            rowA[k] = a; rowB[k] = b;
        }
        if (half == 0) {
            P[(q * 64 + slA) * WSTRIDE + 64] = -divA;
            P[(q * 64 + slB) * WSTRIDE + 64] = -divB;
        }
    }
    __syncthreads();

    // gather: out[s][d] = sum_q P[q][s][d] (+ b2[d] for d<64), coalesced store
    {
        float* outp = out + (size_t)blockIdx.x * SAMP_PER_BLK * (D_DIM + 1);
        for (int i = tid; i < SAMP_PER_BLK * (D_DIM + 1); i += 256) {
            int s = i / (D_DIM + 1);
            int d = i - s * (D_DIM + 1);
            const float* col = P + s * WSTRIDE + d;
            float v = (col[0] + col[64 * WSTRIDE])
                    + (col[128 * WSTRIDE] + col[192 * WSTRIDE]);
            if (d < D_DIM) v += b2s[d];
            outp[i] = v;
        }
    }
}

extern "C" void kernel_launch(void* const* d_in, const int* in_sizes, int n_in,
                              void* d_out, int out_size)
{
    const float* t  = (const float*)d_in[0];
    const float* y  = (const float*)d_in[1];
    const float* W1 = (const float*)d_in[2];
    const float* b1 = (const float*)d_in[3];
    const float* wt = (const float*)d_in[4];
    const float* W2 = (const float*)d_in[5];
    const float* b2 = (const float*)d_in[6];
    float* out = (float*)d_out;

    const int smem_bytes =
        (H_DIM * WSTRIDE * 2) * 4      // W1T + W2s (W2s doubles as transpose scratch)
        + H_DIM * 8                    // metas (float2)
        + D_DIM * 4;                   // b2

    cudaFuncSetAttribute(ode_fused_kernel,
                         cudaFuncAttributeMaxDynamicSharedMemorySize, smem_bytes);

    dim3 grid(N_SAMP / SAMP_PER_BLK);   // 128
    dim3 block(256);
    ode_fused_kernel<<<grid, block, smem_bytes>>>(t, y, W1, b1, wt, W2, b2, out);
}

// round 16
// speedup vs baseline: 1.1086x; 1.0302x over previous
#include <cuda_runtime.h>
#include <cuda_bf16.h>

// ODEfunc: dy = tanh(y@W1 + t*wt + b1) @ W2 + b2 ; div_i = sum_h sech2(z_h)*c_h
// with c_h = sum_d W1[d,h]*W2[h,d]  (analytic trace of the Jacobian).
// Output: [N, D+1] = [dy | -div]
//
// Main loop `unroll 4` (4x scheduling window: 16 independent activation
// chains; ptxas software-pipelines using the ~60-reg headroom from the R8
// traffic fix). metas.x pre-scaled by K so the ex2 argument is a single FMA.

#define N_SAMP 8192
#define D_DIM  64
#define H_DIM  256

#define SAMP_PER_BLK 64
#define WSTRIDE 68     // floats; 272B rows -> 16B aligned
#define TSTRIDE 260    // scratch transpose tile row stride (floats)

typedef unsigned long long ull;

__device__ __forceinline__ ull pack2(float lo, float hi) {
    ull r; asm("mov.b64 %0, {%1, %2};" : "=l"(r) : "f"(lo), "f"(hi)); return r;
}
__device__ __forceinline__ void unpack2(ull v, float& lo, float& hi) {
    asm("mov.b64 {%0, %1}, %2;" : "=f"(lo), "=f"(hi) : "l"(v));
}
__device__ __forceinline__ float rcp_approx(float x) {
    float r; asm("rcp.approx.f32 %0, %1;" : "=f"(r) : "f"(x)); return r;
}
__device__ __forceinline__ float ex2_approx(float x) {
    float r; asm("ex2.approx.f32 %0, %1;" : "=f"(r) : "f"(x)); return r;
}
#define FMA2(d, a, b, c) asm("fma.rn.f32x2 %0, %1, %2, %3;" : "=l"(d) : "l"(a), "l"(b), "l"(c))

__global__ void __launch_bounds__(256, 1)
ode_fused_kernel(const float* __restrict__ t_in,
                 const float* __restrict__ y_g,
                 const float* __restrict__ W1_g,   // [D, H] row-major
                 const float* __restrict__ b1_g,   // [H]
                 const float* __restrict__ wt_g,   // [H]
                 const float* __restrict__ W2_g,   // [H, D] row-major
                 const float* __restrict__ b2_g,   // [D]
                 float* __restrict__ out)          // [N, D+1]
{
    extern __shared__ float sm[];
    float*  W1T   = sm;                          // [H][WSTRIDE]; later reused as P partial tile
    float*  W2s   = W1T + H_DIM * WSTRIDE;       // [H][WSTRIDE]; first used as transpose scratch T
    float2* metas = (float2*)(W2s + H_DIM * WSTRIDE); // [H] : {K*(t*wt+b1), c_h}
    float*  b2s   = (float*)(metas + H_DIM);     // [D]
    float*  T     = W2s;                         // scratch: [D][TSTRIDE]

    const int tid  = threadIdx.x;
    const int lane = tid & 31;
    const int wid  = tid >> 5;
    const int q    = wid >> 1;     // h-chunk 0..3 (64 h each)
    const int set  = wid & 1;      // sample 32-group 0/1
    const int p    = lane & 15;    // sample-pair index
    const int half = lane >> 4;    // D-half 0/1
    const int slA  = set * 32 + p;         // local sample A (0..63)
    const int slB  = slA + 16;             // local sample B
    const int sgA  = blockIdx.x * SAMP_PER_BLK + slA;

    const float t = t_in[0];
    const float K = 2.8853900817779268f;   // 2/ln(2)

    // ---- load y halves for both samples (16 ull each) ----
    ull ya[16], yb[16];
    {
        const ulonglong2* A = (const ulonglong2*)(y_g + (size_t)sgA * D_DIM + half * 32);
        const ulonglong2* B = (const ulonglong2*)(y_g + (size_t)(sgA + 16) * D_DIM + half * 32);
        #pragma unroll
        for (int i = 0; i < 8; i++) {
            ulonglong2 a = A[i], b = B[i];
            ya[2*i] = a.x; ya[2*i+1] = a.y;
            yb[2*i] = b.x; yb[2*i+1] = b.y;
        }
    }

    // ---- Step A: W1 [k][h] -> scratch T[k][h] (coalesced LDG.128, conflict-free STS.128) ----
    {
        const float4* w1v = (const float4*)W1_g;
        #pragma unroll
        for (int j = 0; j < 16; j++) {
            int v  = tid + 256 * j;
            int k  = v >> 6;
            int hq = v & 63;
            *(float4*)(T + k * TSTRIDE + 4 * hq) = w1v[v];
        }
    }
    __syncthreads();

    // ---- Step B: transpose T -> W1T[h][k] ----
    {
        const int h = tid;
        #pragma unroll
        for (int j = 0; j < 16; j++) {
            float4 r;
            r.x = T[(4*j + 0) * TSTRIDE + h];
            r.y = T[(4*j + 1) * TSTRIDE + h];
            r.z = T[(4*j + 2) * TSTRIDE + h];
            r.w = T[(4*j + 3) * TSTRIDE + h];
            *(float4*)(W1T + h * WSTRIDE + 4*j) = r;
        }
    }
    __syncthreads();   // T reads done -> safe to overwrite with W2s

    // ---- W2 [h][d] -> W2s[h][d] ----
    {
        const float4* w2v = (const float4*)W2_g;
        #pragma unroll
        for (int j = 0; j < 16; j++) {
            int v  = tid + 256 * j;
            int h  = v >> 4;
            int dq = v & 15;
            *(float4*)(W2s + h * WSTRIDE + 4 * dq) = w2v[v];
        }
        if (tid < D_DIM) b2s[tid] = b2_g[tid];
    }
    __syncthreads();

    // ---- per-h meta: K*(t*wt+b1) and Jacobian-trace weight c_h ----
    {
        int h = tid;
        const float4* u4 = (const float4*)(W1T + h * WSTRIDE);
        const float4* v4 = (const float4*)(W2s + h * WSTRIDE);
        float ca = 0.f, cb = 0.f, cc = 0.f, cd = 0.f;
        #pragma unroll
        for (int k = 0; k < 16; k++) {
            float4 u = u4[k], v = v4[k];
            ca += u.x * v.x; cb += u.y * v.y; cc += u.z * v.z; cd += u.w * v.w;
        }
        metas[h] = make_float2(K * fmaf(t, wt_g[h], b1_g[h]), (ca + cb) + (cc + cd));
    }
    __syncthreads();

    // ---- main loop: 2 h per body, unroll 4 -> 8-h scheduling window ----
    ull dyA[16], dyB[16];
    #pragma unroll
    for (int d = 0; d < 16; d++) { dyA[d] = 0ull; dyB[d] = 0ull; }
    float divA = 0.f, divB = 0.f;

    const int h0 = q * 64;
    #pragma unroll 4
    for (int i = 0; i < 32; i++) {
        const int ha = h0 + 2 * i;
        const int hb = ha + 1;

        // --- z halves for ha (both samples): 32 FMA2, 8 LDS.128 ---
        const ulonglong2* w1a = (const ulonglong2*)(W1T + ha * WSTRIDE + half * 32);
        ull uA0 = 0ull, uA1 = 0ull, vA0 = 0ull, vA1 = 0ull;
        #pragma unroll
        for (int k = 0; k < 8; k++) {
            ulonglong2 w = w1a[k];
            FMA2(uA0, ya[2*k+0], w.x, uA0);
            FMA2(uA1, ya[2*k+1], w.y, uA1);
            FMA2(vA0, yb[2*k+0], w.x, vA0);
            FMA2(vA1, yb[2*k+1], w.y, vA1);
        }
        float2 ma = metas[ha];
        float x0, x1, x2, x3;
        unpack2(uA0, x0, x1); unpack2(uA1, x2, x3);
        float zAh = (x0 + x1) + (x2 + x3);
        unpack2(vA0, x0, x1); unpack2(vA1, x2, x3);
        float zBh = (x0 + x1) + (x2 + x3);
        zAh += __shfl_xor_sync(0xffffffffu, zAh, 16);
        zBh += __shfl_xor_sync(0xffffffffu, zBh, 16);
        float eA = ex2_approx(fmaf(K, zAh, ma.x));     // MUFU chains ha start
        float eB = ex2_approx(fmaf(K, zBh, ma.x));

        // --- z halves for hb: execute under ha's MUFU latency ---
        const ulonglong2* w1b = (const ulonglong2*)(W1T + hb * WSTRIDE + half * 32);
        ull uB0 = 0ull, uB1 = 0ull, vB0 = 0ull, vB1 = 0ull;
        #pragma unroll
        for (int k = 0; k < 8; k++) {
            ulonglong2 w = w1b[k];
            FMA2(uB0, ya[2*k+0], w.x, uB0);
            FMA2(uB1, ya[2*k+1], w.y, uB1);
            FMA2(vB0, yb[2*k+0], w.x, vB0);
            FMA2(vB1, yb[2*k+1], w.y, vB1);
        }
        float2 mb = metas[hb];
        unpack2(uB0, x0, x1); unpack2(uB1, x2, x3);
        float zAh2 = (x0 + x1) + (x2 + x3);
        unpack2(vB0, x0, x1); unpack2(vB1, x2, x3);
        float zBh2 = (x0 + x1) + (x2 + x3);
        zAh2 += __shfl_xor_sync(0xffffffffu, zAh2, 16);
        zBh2 += __shfl_xor_sync(0xffffffffu, zBh2, 16);

        float uAa = 2.0f * rcp_approx(eA + 1.0f);      // ha MUFU chains continue
        float uBa = 2.0f * rcp_approx(eB + 1.0f);
        float eA2 = ex2_approx(fmaf(K, zAh2, mb.x));   // hb MUFU chains start
        float eB2 = ex2_approx(fmaf(K, zBh2, mb.x));
        float aA = 1.0f - uAa;
        float aB = 1.0f - uBa;
        divA = fmaf(uAa * (2.0f - uAa), ma.y, divA);
        divB = fmaf(uBa * (2.0f - uBa), ma.y, divB);

        // --- dy += a * W2[ha] (halves): 32 FMA2, 8 LDS.128; covers hb MUFU ---
        ull aAp = pack2(aA, aA), aBp = pack2(aB, aB);
        const ulonglong2* w2a = (const ulonglong2*)(W2s + ha * WSTRIDE + half * 32);
        #pragma unroll
        for (int k = 0; k < 8; k++) {
            ulonglong2 w = w2a[k];
            FMA2(dyA[2*k+0], aAp, w.x, dyA[2*k+0]);
            FMA2(dyA[2*k+1], aAp, w.y, dyA[2*k+1]);
            FMA2(dyB[2*k+0], aBp, w.x, dyB[2*k+0]);
            FMA2(dyB[2*k+1], aBp, w.y, dyB[2*k+1]);
        }

        float uA2 = 2.0f * rcp_approx(eA2 + 1.0f);
        float uB2 = 2.0f * rcp_approx(eB2 + 1.0f);
        float aA2 = 1.0f - uA2;
        float aB2 = 1.0f - uB2;
        divA = fmaf(uA2 * (2.0f - uA2), mb.y, divA);
        divB = fmaf(uB2 * (2.0f - uB2), mb.y, divB);

        // --- dy += a * W2[hb] (halves): overlaps next iteration's loads ---
        ull aA2p = pack2(aA2, aA2), aB2p = pack2(aB2, aB2);
        const ulonglong2* w2b = (const ulonglong2*)(W2s + hb * WSTRIDE + half * 32);
        #pragma unroll
        for (int k = 0; k < 8; k++) {
            ulonglong2 w = w2b[k];
            FMA2(dyA[2*k+0], aA2p, w.x, dyA[2*k+0]);
            FMA2(dyA[2*k+1], aA2p, w.y, dyA[2*k+1]);
            FMA2(dyB[2*k+0], aB2p, w.x, dyB[2*k+0]);
            FMA2(dyB[2*k+1], aB2p, w.y, dyB[2*k+1]);
        }
    }

    // ---- parallel epilogue: partials into P (reuses W1T), one gather ----
    float* P = W1T;   // row = q*64 + local_sample, cols [half*32, half*32+32), col 64 = -div
    __syncthreads();  // all W1T reads complete before overwrite
    {
        ulonglong2* rowA = (ulonglong2*)(P + (q * 64 + slA) * WSTRIDE + half * 32);
        ulonglong2* rowB = (ulonglong2*)(P + (q * 64 + slB) * WSTRIDE + half * 32);
        #pragma unroll
        for (int k = 0; k < 8; k++) {
            ulonglong2 a; a.x = dyA[2*k]; a.y = dyA[2*k+1];
            ulonglong2 b; b.x = dyB[2*k]; b.y = dyB[2*k+1];
            rowA[k] = a; rowB[k] = b;
        }
        if (half == 0) {
            P[(q * 64 + slA) * WSTRIDE + 64] = -divA;
            P[(q * 64 + slB) * WSTRIDE + 64] = -divB;
        }
    }
    __syncthreads();

    // gather: out[s][d] = sum_q P[q][s][d] (+ b2[d] for d<64), coalesced store
    {
        float* outp = out + (size_t)blockIdx.x * SAMP_PER_BLK * (D_DIM + 1);
        for (int i = tid; i < SAMP_PER_BLK * (D_DIM + 1); i += 256) {
            int s = i / (D_DIM + 1);
            int d = i - s * (D_DIM + 1);
            const float* col = P + s * WSTRIDE + d;
            float v = (col[0] + col[64 * WSTRIDE])
                    + (col[128 * WSTRIDE] + col[192 * WSTRIDE]);
            if (d < D_DIM) v += b2s[d];
            outp[i] = v;
        }
    }
}

extern "C" void kernel_launch(void* const* d_in, const int* in_sizes, int n_in,
                              void* d_out, int out_size)
{
    const float* t  = (const float*)d_in[0];
    const float* y  = (const float*)d_in[1];
    const float* W1 = (const float*)d_in[2];
    const float* b1 = (const float*)d_in[3];
    const float* wt = (const float*)d_in[4];
    const float* W2 = (const float*)d_in[5];
    const float* b2 = (const float*)d_in[6];
    float* out = (float*)d_out;

    const int smem_bytes =
        (H_DIM * WSTRIDE * 2) * 4      // W1T + W2s (W2s doubles as transpose scratch)
        + H_DIM * 8                    // metas (float2)
        + D_DIM * 4;                   // b2

    cudaFuncSetAttribute(ode_fused_kernel,
                         cudaFuncAttributeMaxDynamicSharedMemorySize, smem_bytes);

    dim3 grid(N_SAMP / SAMP_PER_BLK);   // 128
    dim3 block(256);
    ode_fused_kernel<<<grid, block, smem_bytes>>>(t, y, W1, b1, wt, W2, b2, out);
}